// round 1
// baseline (speedup 1.0000x reference)
#include <cuda_runtime.h>
#include <math.h>

#define BATCH 4
#define FRAMES 120
#define JOINTS 25
#define NTOK 3000          // FRAMES*JOINTS
#define DIM 512
#define NH 8
#define DH 64
#define HD 512             // NH*DH
#define NROWS (BATCH*NTOK) // 12000
#define NEGV (-9e15f)

// scratch: q,k,v in [B,H,N,DH] layout
__device__ float g_q[BATCH*NH*NTOK*DH];
__device__ float g_k[BATCH*NH*NTOK*DH];
__device__ float g_v[BATCH*NH*NTOK*DH];

// ---------------------------------------------------------------------------
// Projection: X[12000,512] @ W[512,512] + b  -> scatter to [B,H,N,DH]
// blockIdx.z selects q/k/v (v gets relu). 64x64 tile, 16x16 threads, 4x4 each.
// ---------------------------------------------------------------------------
__global__ void proj_kernel(const float* __restrict__ x,
                            const float* __restrict__ Wq, const float* __restrict__ bq,
                            const float* __restrict__ Wk, const float* __restrict__ bk,
                            const float* __restrict__ Wv, const float* __restrict__ bv)
{
    __shared__ float As[16][64];
    __shared__ float Bs[16][64];
    const int tx = threadIdx.x, ty = threadIdx.y;
    const int tid = ty * 16 + tx;
    const int m0 = blockIdx.x * 64;
    const int n0 = blockIdx.y * 64;
    const int which = blockIdx.z;

    const float* W    = (which == 0) ? Wq : (which == 1) ? Wk : Wv;
    const float* bias = (which == 0) ? bq : (which == 1) ? bk : bv;
    float* outp       = (which == 0) ? g_q : (which == 1) ? g_k : g_v;

    float acc[4][4] = {};
    for (int k0 = 0; k0 < DIM; k0 += 16) {
        #pragma unroll
        for (int i = 0; i < 4; i++) {
            int idx = tid + i * 256;
            int m = idx >> 4, kk = idx & 15;
            int gm = m0 + m;
            As[kk][m] = (gm < NROWS) ? x[(size_t)gm * DIM + k0 + kk] : 0.f;
        }
        #pragma unroll
        for (int i = 0; i < 4; i++) {
            int idx = tid + i * 256;
            int kk = idx >> 6, n = idx & 63;
            Bs[kk][n] = W[(size_t)(k0 + kk) * HD + n0 + n];
        }
        __syncthreads();
        #pragma unroll
        for (int kk = 0; kk < 16; kk++) {
            float4 a4 = *(const float4*)&As[kk][ty * 4];
            float4 b4 = *(const float4*)&Bs[kk][tx * 4];
            float av[4] = {a4.x, a4.y, a4.z, a4.w};
            float bv4[4] = {b4.x, b4.y, b4.z, b4.w};
            #pragma unroll
            for (int i = 0; i < 4; i++)
                #pragma unroll
                for (int j = 0; j < 4; j++)
                    acc[i][j] = fmaf(av[i], bv4[j], acc[i][j]);
        }
        __syncthreads();
    }
    #pragma unroll
    for (int i = 0; i < 4; i++) {
        int gm = m0 + ty * 4 + i;
        if (gm >= NROWS) continue;
        int b = gm / NTOK, n = gm % NTOK;
        #pragma unroll
        for (int j = 0; j < 4; j++) {
            int gc = n0 + tx * 4 + j;
            float v = acc[i][j] + bias[gc];
            if (which == 2) v = fmaxf(v, 0.f);
            int h = gc >> 6, d = gc & 63;
            outp[((size_t)((b * NH + h) * NTOK) + n) * DH + d] = v;
        }
    }
}

// ---------------------------------------------------------------------------
// Scores: S = Q @ K^T * 0.125, masked (same frame && q!=k -> NEG).
// Written raw into the attn region of d_out. 64x64 tile per (b,h).
// ---------------------------------------------------------------------------
__global__ void scores_kernel(float* __restrict__ attn)
{
    __shared__ float As[16][64];
    __shared__ float Bs[16][64];
    const int tx = threadIdx.x, ty = threadIdx.y;
    const int tid = ty * 16 + tx;
    const int m0 = blockIdx.x * 64;
    const int n0 = blockIdx.y * 64;
    const int bh = blockIdx.z;

    const float* Q = g_q + (size_t)bh * NTOK * DH;
    const float* K = g_k + (size_t)bh * NTOK * DH;

    float acc[4][4] = {};
    #pragma unroll
    for (int k0 = 0; k0 < DH; k0 += 16) {
        #pragma unroll
        for (int i = 0; i < 4; i++) {
            int idx = tid + i * 256;
            int m = idx >> 4, kk = idx & 15;
            int gm = m0 + m;
            As[kk][m] = (gm < NTOK) ? Q[(size_t)gm * DH + k0 + kk] : 0.f;
        }
        #pragma unroll
        for (int i = 0; i < 4; i++) {
            int idx = tid + i * 256;
            int n = idx >> 4, kk = idx & 15;
            int gn = n0 + n;
            Bs[kk][n] = (gn < NTOK) ? K[(size_t)gn * DH + k0 + kk] : 0.f;
        }
        __syncthreads();
        #pragma unroll
        for (int kk = 0; kk < 16; kk++) {
            float4 a4 = *(const float4*)&As[kk][ty * 4];
            float4 b4 = *(const float4*)&Bs[kk][tx * 4];
            float av[4] = {a4.x, a4.y, a4.z, a4.w};
            float bv4[4] = {b4.x, b4.y, b4.z, b4.w};
            #pragma unroll
            for (int i = 0; i < 4; i++)
                #pragma unroll
                for (int j = 0; j < 4; j++)
                    acc[i][j] = fmaf(av[i], bv4[j], acc[i][j]);
        }
        __syncthreads();
    }
    float* Abh = attn + (size_t)bh * NTOK * NTOK;
    #pragma unroll
    for (int i = 0; i < 4; i++) {
        int qn = m0 + ty * 4 + i;
        if (qn >= NTOK) continue;
        int qf = qn / JOINTS;
        #pragma unroll
        for (int j = 0; j < 4; j++) {
            int kn = n0 + tx * 4 + j;
            if (kn >= NTOK) continue;
            float s = acc[i][j] * 0.125f;
            int kf = kn / JOINTS;
            if (qf == kf && qn != kn) s = NEGV;
            Abh[(size_t)qn * NTOK + kn] = s;
        }
    }
}

// ---------------------------------------------------------------------------
// Row softmax in place: one block per row, 3000 floats held in registers
// (24 per thread x 128 threads). Single gmem read + single write per element.
// ---------------------------------------------------------------------------
__global__ void softmax_kernel(float* __restrict__ attn)
{
    const size_t row = blockIdx.x;
    float* p = attn + row * (size_t)NTOK;
    const int t = threadIdx.x;
    const int lane = t & 31, warp = t >> 5;
    __shared__ float red[4];

    float vals[24];
    float mx = NEGV;
    #pragma unroll
    for (int i = 0; i < 24; i++) {
        int idx = t + i * 128;
        float v = (idx < NTOK) ? p[idx] : NEGV;
        vals[i] = v;
        mx = fmaxf(mx, v);
    }
    #pragma unroll
    for (int o = 16; o; o >>= 1) mx = fmaxf(mx, __shfl_xor_sync(0xffffffffu, mx, o));
    if (lane == 0) red[warp] = mx;
    __syncthreads();
    mx = fmaxf(fmaxf(red[0], red[1]), fmaxf(red[2], red[3]));
    __syncthreads();

    float s = 0.f;
    #pragma unroll
    for (int i = 0; i < 24; i++) {
        float e = expf(vals[i] - mx);   // masked (-9e15) -> exactly 0
        vals[i] = e;
        s += e;
    }
    #pragma unroll
    for (int o = 16; o; o >>= 1) s += __shfl_xor_sync(0xffffffffu, s, o);
    if (lane == 0) red[warp] = s;
    __syncthreads();
    s = red[0] + red[1] + red[2] + red[3];
    float inv = 1.f / s;

    #pragma unroll
    for (int i = 0; i < 24; i++) {
        int idx = t + i * 128;
        if (idx < NTOK) p[idx] = vals[i] * inv;
    }
}

// ---------------------------------------------------------------------------
// Out: O[m, 64] = P[m, :3000] @ V[:3000, 64] per (b,h); scatter to [B,N,H*DH].
// ---------------------------------------------------------------------------
__global__ void out_kernel(const float* __restrict__ attn, float* __restrict__ out)
{
    __shared__ float As[16][64];
    __shared__ float Bs[16][64];
    const int tx = threadIdx.x, ty = threadIdx.y;
    const int tid = ty * 16 + tx;
    const int m0 = blockIdx.x * 64;
    const int bh = blockIdx.z;

    const float* P = attn + (size_t)bh * NTOK * NTOK;
    const float* V = g_v + (size_t)bh * NTOK * DH;

    float acc[4][4] = {};
    for (int k0 = 0; k0 < NTOK; k0 += 16) {
        #pragma unroll
        for (int i = 0; i < 4; i++) {
            int idx = tid + i * 256;
            int m = idx >> 4, kk = idx & 15;
            int gm = m0 + m, gk = k0 + kk;
            As[kk][m] = (gm < NTOK && gk < NTOK) ? P[(size_t)gm * NTOK + gk] : 0.f;
        }
        #pragma unroll
        for (int i = 0; i < 4; i++) {
            int idx = tid + i * 256;
            int kk = idx >> 6, d = idx & 63;
            int gk = k0 + kk;
            Bs[kk][d] = (gk < NTOK) ? V[(size_t)gk * DH + d] : 0.f;
        }
        __syncthreads();
        #pragma unroll
        for (int kk = 0; kk < 16; kk++) {
            float4 a4 = *(const float4*)&As[kk][ty * 4];
            float4 b4 = *(const float4*)&Bs[kk][tx * 4];
            float av[4] = {a4.x, a4.y, a4.z, a4.w};
            float bv4[4] = {b4.x, b4.y, b4.z, b4.w};
            #pragma unroll
            for (int i = 0; i < 4; i++)
                #pragma unroll
                for (int j = 0; j < 4; j++)
                    acc[i][j] = fmaf(av[i], bv4[j], acc[i][j]);
        }
        __syncthreads();
    }
    const int b = bh / NH, h = bh % NH;
    #pragma unroll
    for (int i = 0; i < 4; i++) {
        int gm = m0 + ty * 4 + i;
        if (gm >= NTOK) continue;
        #pragma unroll
        for (int j = 0; j < 4; j++) {
            int d = tx * 4 + j;
            out[((size_t)(b * NTOK + gm)) * HD + h * DH + d] = acc[i][j];
        }
    }
}

extern "C" void kernel_launch(void* const* d_in, const int* in_sizes, int n_in,
                              void* d_out, int out_size)
{
    const float* x  = (const float*)d_in[0];
    const float* Wq = (const float*)d_in[1];
    const float* bq = (const float*)d_in[2];
    const float* Wk = (const float*)d_in[3];
    const float* bk = (const float*)d_in[4];
    const float* Wv = (const float*)d_in[5];
    const float* bv = (const float*)d_in[6];

    float* out  = (float*)d_out;                       // [B, N, H*DH]
    float* attn = out + (size_t)BATCH * NTOK * HD;     // [B, H, N, N]

    dim3 blk(16, 16);

    // projections: 12000x512 output, 3 matrices
    dim3 gproj((NROWS + 63) / 64, HD / 64, 3);         // 188 x 8 x 3
    proj_kernel<<<gproj, blk>>>(x, Wq, bq, Wk, bk, Wv, bv);

    // scores (written raw into attn region)
    dim3 gsc((NTOK + 63) / 64, (NTOK + 63) / 64, BATCH * NH);  // 47 x 47 x 32
    scores_kernel<<<gsc, blk>>>(attn);

    // in-place row softmax
    softmax_kernel<<<BATCH * NH * NTOK, 128>>>(attn);

    // out = P @ V
    dim3 go((NTOK + 63) / 64, 1, BATCH * NH);          // 47 x 1 x 32
    out_kernel<<<go, blk>>>(attn, out);
}

// round 2
// speedup vs baseline: 1.4543x; 1.4543x over previous
#include <cuda_runtime.h>
#include <math.h>

#define BATCH 4
#define FRAMES 120
#define JOINTS 25
#define NTOK 3000
#define DIM 512
#define NH 8
#define DH 64
#define HD 512
#define NROWS (BATCH*NTOK)
#define NEGV (-9e15f)

typedef unsigned long long ull;

// scratch: q,k,v in [B,H,N,DH] layout
__device__ float g_q[BATCH*NH*NTOK*DH];
__device__ float g_k[BATCH*NH*NTOK*DH];
__device__ float g_v[BATCH*NH*NTOK*DH];

// ---- f32x2 helpers -------------------------------------------------------
__device__ __forceinline__ ull dup2(float x) {
    ull r; asm("mov.b64 %0, {%1, %1};" : "=l"(r) : "f"(x)); return r;
}
__device__ __forceinline__ void fma2(ull& d, ull a, ull b) {
    asm("fma.rn.f32x2 %0, %1, %2, %0;" : "+l"(d) : "l"(a), "l"(b));
}
__device__ __forceinline__ float2 unpack2(ull v) {
    float2 f; asm("mov.b64 {%0, %1}, %2;" : "=f"(f.x), "=f"(f.y) : "l"(v)); return f;
}

// ---------------------------------------------------------------------------
// Projection: X[12000,512] @ W[512,512] + b -> scatter [B,H,N,DH].
// 128x128 tile, 256 threads, 8x8 per thread (4+4 split), f32x2 FMA.
// ---------------------------------------------------------------------------
__global__ void proj_kernel(const float* __restrict__ x,
                            const float* __restrict__ Wq, const float* __restrict__ bq,
                            const float* __restrict__ Wk, const float* __restrict__ bk,
                            const float* __restrict__ Wv, const float* __restrict__ bv)
{
    __shared__ float As[16][132];   // [k][m] transposed
    __shared__ float Bs[16][132];   // [k][n]
    const int tid = threadIdx.x;
    const int tx = tid & 15, ty = tid >> 4;
    const int m0 = blockIdx.x * 128;
    const int n0 = blockIdx.y * 128;
    const int which = blockIdx.z;

    const float* W    = (which == 0) ? Wq : (which == 1) ? Wk : Wv;
    const float* bias = (which == 0) ? bq : (which == 1) ? bk : bv;
    float* outp       = (which == 0) ? g_q : (which == 1) ? g_k : g_v;

    ull acc[8][4] = {};

    for (int k0 = 0; k0 < DIM; k0 += 16) {
        #pragma unroll
        for (int r = 0; r < 2; r++) {
            int p = tid + r * 256;          // [0,512)
            int m = p >> 2, kg = (p & 3) * 4;
            int gm = m0 + m;
            float4 v = make_float4(0.f, 0.f, 0.f, 0.f);
            if (gm < NROWS) v = *(const float4*)&x[(size_t)gm * DIM + k0 + kg];
            As[kg + 0][m] = v.x; As[kg + 1][m] = v.y;
            As[kg + 2][m] = v.z; As[kg + 3][m] = v.w;
        }
        #pragma unroll
        for (int r = 0; r < 2; r++) {
            int p = tid + r * 256;
            int kk = p >> 5, ng = (p & 31) * 4;
            float4 v = *(const float4*)&W[(size_t)(k0 + kk) * HD + n0 + ng];
            *(float4*)&Bs[kk][ng] = v;
        }
        __syncthreads();
        #pragma unroll
        for (int kk = 0; kk < 16; kk++) {
            float4 a0 = *(const float4*)&As[kk][ty * 4];
            float4 a1 = *(const float4*)&As[kk][64 + ty * 4];
            ull aa[8];
            aa[0] = dup2(a0.x); aa[1] = dup2(a0.y); aa[2] = dup2(a0.z); aa[3] = dup2(a0.w);
            aa[4] = dup2(a1.x); aa[5] = dup2(a1.y); aa[6] = dup2(a1.z); aa[7] = dup2(a1.w);
            ull bb[4];
            bb[0] = *(const ull*)&Bs[kk][tx * 4];
            bb[1] = *(const ull*)&Bs[kk][tx * 4 + 2];
            bb[2] = *(const ull*)&Bs[kk][64 + tx * 4];
            bb[3] = *(const ull*)&Bs[kk][64 + tx * 4 + 2];
            #pragma unroll
            for (int i = 0; i < 8; i++)
                #pragma unroll
                for (int j = 0; j < 4; j++)
                    fma2(acc[i][j], aa[i], bb[j]);
        }
        __syncthreads();
    }

    #pragma unroll
    for (int i = 0; i < 8; i++) {
        int gm = m0 + ((i < 4) ? (ty * 4 + i) : (64 + ty * 4 + i - 4));
        if (gm >= NROWS) continue;
        int b = gm / NTOK, n = gm % NTOK;
        #pragma unroll
        for (int j = 0; j < 4; j++) {
            int c = (j < 2) ? (tx * 4 + j * 2) : (64 + tx * 4 + (j - 2) * 2);
            float2 v2 = unpack2(acc[i][j]);
            #pragma unroll
            for (int e = 0; e < 2; e++) {
                int gc = n0 + c + e;
                float v = ((e == 0) ? v2.x : v2.y) + bias[gc];
                if (which == 2) v = fmaxf(v, 0.f);
                int h = gc >> 6, d = gc & 63;
                outp[((size_t)((b * NH + h) * NTOK) + n) * DH + d] = v;
            }
        }
    }
}

// ---------------------------------------------------------------------------
// Scores: S = Q @ K^T * 0.125 + mask, per (b,h). 128x128 tile, K=64 in one
// shot (both tiles fully resident in smem), f32x2 FMA.
// ---------------------------------------------------------------------------
__global__ void scores_kernel(float* __restrict__ attn)
{
    __shared__ float Qs[64][132];   // [d][m]
    __shared__ float Ks[64][132];   // [d][n]
    const int tid = threadIdx.x;
    const int tx = tid & 15, ty = tid >> 4;
    const int m0 = blockIdx.x * 128;
    const int n0 = blockIdx.y * 128;
    const int bh = blockIdx.z;

    const float* Q = g_q + (size_t)bh * NTOK * DH;
    const float* K = g_k + (size_t)bh * NTOK * DH;

    #pragma unroll
    for (int r = 0; r < 8; r++) {
        int p = tid + r * 256;           // [0,2048)
        int m = p >> 4, dg = (p & 15) * 4;
        float4 vq = make_float4(0.f, 0.f, 0.f, 0.f);
        float4 vk = make_float4(0.f, 0.f, 0.f, 0.f);
        if (m0 + m < NTOK) vq = *(const float4*)&Q[(size_t)(m0 + m) * DH + dg];
        if (n0 + m < NTOK) vk = *(const float4*)&K[(size_t)(n0 + m) * DH + dg];
        Qs[dg + 0][m] = vq.x; Qs[dg + 1][m] = vq.y; Qs[dg + 2][m] = vq.z; Qs[dg + 3][m] = vq.w;
        Ks[dg + 0][m] = vk.x; Ks[dg + 1][m] = vk.y; Ks[dg + 2][m] = vk.z; Ks[dg + 3][m] = vk.w;
    }
    __syncthreads();

    ull acc[8][4] = {};
    #pragma unroll 8
    for (int kk = 0; kk < 64; kk++) {
        float4 a0 = *(const float4*)&Qs[kk][ty * 4];
        float4 a1 = *(const float4*)&Qs[kk][64 + ty * 4];
        ull aa[8];
        aa[0] = dup2(a0.x); aa[1] = dup2(a0.y); aa[2] = dup2(a0.z); aa[3] = dup2(a0.w);
        aa[4] = dup2(a1.x); aa[5] = dup2(a1.y); aa[6] = dup2(a1.z); aa[7] = dup2(a1.w);
        ull bb[4];
        bb[0] = *(const ull*)&Ks[kk][tx * 4];
        bb[1] = *(const ull*)&Ks[kk][tx * 4 + 2];
        bb[2] = *(const ull*)&Ks[kk][64 + tx * 4];
        bb[3] = *(const ull*)&Ks[kk][64 + tx * 4 + 2];
        #pragma unroll
        for (int i = 0; i < 8; i++)
            #pragma unroll
            for (int j = 0; j < 4; j++)
                fma2(acc[i][j], aa[i], bb[j]);
    }

    float* Abh = attn + (size_t)bh * NTOK * NTOK;
    #pragma unroll
    for (int i = 0; i < 8; i++) {
        int qn = m0 + ((i < 4) ? (ty * 4 + i) : (64 + ty * 4 + i - 4));
        if (qn >= NTOK) continue;
        int qf = qn / JOINTS;
        #pragma unroll
        for (int j = 0; j < 4; j++) {
            int c = (j < 2) ? (tx * 4 + j * 2) : (64 + tx * 4 + (j - 2) * 2);
            float2 v2 = unpack2(acc[i][j]);
            #pragma unroll
            for (int e = 0; e < 2; e++) {
                int kn = n0 + c + e;
                if (kn >= NTOK) continue;
                float s = ((e == 0) ? v2.x : v2.y) * 0.125f;
                int kf = kn / JOINTS;
                if (qf == kf && qn != kn) s = NEGV;
                Abh[(size_t)qn * NTOK + kn] = s;
            }
        }
    }
}

// ---------------------------------------------------------------------------
// Row softmax in place: one block per row, 3000 floats in registers.
// ---------------------------------------------------------------------------
__global__ void softmax_kernel(float* __restrict__ attn)
{
    const size_t row = blockIdx.x;
    float* p = attn + row * (size_t)NTOK;
    const int t = threadIdx.x;
    const int lane = t & 31, warp = t >> 5;
    __shared__ float red[4];

    float vals[24];
    float mx = NEGV;
    #pragma unroll
    for (int i = 0; i < 24; i++) {
        int idx = t + i * 128;
        float v = (idx < NTOK) ? p[idx] : NEGV;
        vals[i] = v;
        mx = fmaxf(mx, v);
    }
    #pragma unroll
    for (int o = 16; o; o >>= 1) mx = fmaxf(mx, __shfl_xor_sync(0xffffffffu, mx, o));
    if (lane == 0) red[warp] = mx;
    __syncthreads();
    mx = fmaxf(fmaxf(red[0], red[1]), fmaxf(red[2], red[3]));
    __syncthreads();

    float s = 0.f;
    #pragma unroll
    for (int i = 0; i < 24; i++) {
        float e = expf(vals[i] - mx);
        vals[i] = e;
        s += e;
    }
    #pragma unroll
    for (int o = 16; o; o >>= 1) s += __shfl_xor_sync(0xffffffffu, s, o);
    if (lane == 0) red[warp] = s;
    __syncthreads();
    s = red[0] + red[1] + red[2] + red[3];
    float inv = 1.f / s;

    #pragma unroll
    for (int i = 0; i < 24; i++) {
        int idx = t + i * 128;
        if (idx < NTOK) p[idx] = vals[i] * inv;
    }
}

// ---------------------------------------------------------------------------
// Out: O[128-tile, 64] = P @ V per (b,h). 128 threads (16x8), 8x8 per thread.
// ---------------------------------------------------------------------------
__global__ void out_kernel(const float* __restrict__ attn, float* __restrict__ out)
{
    __shared__ float Ps[16][132];   // [k][m]
    __shared__ float Vs[16][68];    // [k][d]
    const int tid = threadIdx.x;    // 128
    const int tx = tid & 7, ty = tid >> 3;
    const int m0 = blockIdx.x * 128;
    const int bh = blockIdx.z;

    const float* P = attn + (size_t)bh * NTOK * NTOK;
    const float* V = g_v + (size_t)bh * NTOK * DH;

    ull acc[8][4] = {};

    for (int k0 = 0; k0 < NTOK; k0 += 16) {
        #pragma unroll
        for (int r = 0; r < 4; r++) {
            int p = tid + r * 128;       // [0,512)
            int m = p >> 2, kg = (p & 3) * 4;
            int gm = m0 + m;
            float4 v = make_float4(0.f, 0.f, 0.f, 0.f);
            if (gm < NTOK && k0 + kg + 3 < NTOK)
                v = *(const float4*)&P[(size_t)gm * NTOK + k0 + kg];
            else if (gm < NTOK) {
                float* vv = (float*)&v;
                #pragma unroll
                for (int e = 0; e < 4; e++)
                    if (k0 + kg + e < NTOK) vv[e] = P[(size_t)gm * NTOK + k0 + kg + e];
            }
            Ps[kg + 0][m] = v.x; Ps[kg + 1][m] = v.y;
            Ps[kg + 2][m] = v.z; Ps[kg + 3][m] = v.w;
        }
        #pragma unroll
        for (int r = 0; r < 2; r++) {
            int p = tid + r * 128;       // [0,256)
            int kk = p >> 4, ng = (p & 15) * 4;
            float4 v = make_float4(0.f, 0.f, 0.f, 0.f);
            if (k0 + kk < NTOK) v = *(const float4*)&V[(size_t)(k0 + kk) * DH + ng];
            *(float4*)&Vs[kk][ng] = v;
        }
        __syncthreads();
        #pragma unroll
        for (int kk = 0; kk < 16; kk++) {
            float4 a0 = *(const float4*)&Ps[kk][ty * 4];
            float4 a1 = *(const float4*)&Ps[kk][64 + ty * 4];
            ull aa[8];
            aa[0] = dup2(a0.x); aa[1] = dup2(a0.y); aa[2] = dup2(a0.z); aa[3] = dup2(a0.w);
            aa[4] = dup2(a1.x); aa[5] = dup2(a1.y); aa[6] = dup2(a1.z); aa[7] = dup2(a1.w);
            ull bb[4];
            bb[0] = *(const ull*)&Vs[kk][tx * 4];
            bb[1] = *(const ull*)&Vs[kk][tx * 4 + 2];
            bb[2] = *(const ull*)&Vs[kk][32 + tx * 4];
            bb[3] = *(const ull*)&Vs[kk][32 + tx * 4 + 2];
            #pragma unroll
            for (int i = 0; i < 8; i++)
                #pragma unroll
                for (int j = 0; j < 4; j++)
                    fma2(acc[i][j], aa[i], bb[j]);
        }
        __syncthreads();
    }

    const int b = bh / NH, h = bh % NH;
    #pragma unroll
    for (int i = 0; i < 8; i++) {
        int gm = m0 + ((i < 4) ? (ty * 4 + i) : (64 + ty * 4 + i - 4));
        if (gm >= NTOK) continue;
        #pragma unroll
        for (int j = 0; j < 4; j++) {
            int c = (j < 2) ? (tx * 4 + j * 2) : (32 + tx * 4 + (j - 2) * 2);
            float2 v2 = unpack2(acc[i][j]);
            out[((size_t)(b * NTOK + gm)) * HD + h * DH + c]     = v2.x;
            out[((size_t)(b * NTOK + gm)) * HD + h * DH + c + 1] = v2.y;
        }
    }
}

extern "C" void kernel_launch(void* const* d_in, const int* in_sizes, int n_in,
                              void* d_out, int out_size)
{
    const float* x  = (const float*)d_in[0];
    const float* Wq = (const float*)d_in[1];
    const float* bq = (const float*)d_in[2];
    const float* Wk = (const float*)d_in[3];
    const float* bk = (const float*)d_in[4];
    const float* Wv = (const float*)d_in[5];
    const float* bv = (const float*)d_in[6];

    float* out  = (float*)d_out;
    float* attn = out + (size_t)BATCH * NTOK * HD;

    dim3 gproj((NROWS + 127) / 128, HD / 128, 3);                 // 94 x 4 x 3
    proj_kernel<<<gproj, 256>>>(x, Wq, bq, Wk, bk, Wv, bv);

    dim3 gsc((NTOK + 127) / 128, (NTOK + 127) / 128, BATCH * NH); // 24 x 24 x 32
    scores_kernel<<<gsc, 256>>>(attn);

    softmax_kernel<<<BATCH * NH * NTOK, 128>>>(attn);

    dim3 go((NTOK + 127) / 128, 1, BATCH * NH);                   // 24 x 1 x 32
    out_kernel<<<go, 128>>>(attn, out);
}

// round 10
// speedup vs baseline: 2.0034x; 1.3776x over previous
#include <cuda_runtime.h>
#include <cstdint>
#include <math.h>

#define BATCH 4
#define JOINTS 25
#define NTOK 3000
#define DIM 512
#define NH 8
#define DH 64
#define HD 512
#define NROWS (BATCH*NTOK)
#define NEGV (-9e15f)

typedef unsigned long long ull;

// scratch: q,k,v in [B,H,N,DH] layout (full fp32)
__device__ float g_q[BATCH*NH*NTOK*DH];
__device__ float g_k[BATCH*NH*NTOK*DH];
__device__ float g_v[BATCH*NH*NTOK*DH];

// ---------------- f32x2 helpers (proj kernel) ------------------------------
__device__ __forceinline__ ull dup2(float x) {
    ull r; asm("mov.b64 %0, {%1, %1};" : "=l"(r) : "f"(x)); return r;
}
__device__ __forceinline__ void fma2(ull& d, ull a, ull b) {
    asm("fma.rn.f32x2 %0, %1, %2, %0;" : "+l"(d) : "l"(a), "l"(b));
}
__device__ __forceinline__ float2 unpack2(ull v) {
    float2 f; asm("mov.b64 {%0, %1}, %2;" : "=f"(f.x), "=f"(f.y) : "l"(v)); return f;
}
__device__ __forceinline__ float tf32r(float x) {
    float r; asm("cvt.rna.tf32.f32 %0, %1;" : "=f"(r) : "f"(x)); return r;
}

// ---------------- cp.async + mma.sync helpers ------------------------------
__device__ __forceinline__ uint32_t smem_u32(const void* p) {
    uint32_t a;
    asm("{ .reg .u64 t; cvta.to.shared.u64 t, %1; cvt.u32.u64 %0, t; }" : "=r"(a) : "l"(p));
    return a;
}
__device__ __forceinline__ void cpa16(uint32_t dst, const void* src, int bytes) {
    asm volatile("cp.async.ca.shared.global [%0], [%1], 16, %2;"
                 :: "r"(dst), "l"(src), "r"(bytes) : "memory");
}
__device__ __forceinline__ void cpa_commit() {
    asm volatile("cp.async.commit_group;" ::: "memory");
}
__device__ __forceinline__ void cpa_wait0() {
    asm volatile("cp.async.wait_group 0;" ::: "memory");
}
__device__ __forceinline__ void cpa_wait1() {
    asm volatile("cp.async.wait_group 1;" ::: "memory");
}
// D += A(16x8) * B(8x8), tf32 inputs, f32 accum
__device__ __forceinline__ void mma8(float* c, const uint32_t* a, const uint32_t* b) {
    asm volatile(
        "mma.sync.aligned.m16n8k8.row.col.f32.tf32.tf32.f32 "
        "{%0,%1,%2,%3}, {%4,%5,%6,%7}, {%8,%9}, {%0,%1,%2,%3};"
        : "+f"(c[0]), "+f"(c[1]), "+f"(c[2]), "+f"(c[3])
        : "r"(a[0]), "r"(a[1]), "r"(a[2]), "r"(a[3]), "r"(b[0]), "r"(b[1]));
}
__device__ __forceinline__ uint32_t fbits(float x) {
    uint32_t u; asm("mov.b32 %0, %1;" : "=r"(u) : "f"(x)); return u;
}
// split fp32 into tf32 hi + tf32 lo (3xTF32 decomposition)
__device__ __forceinline__ void split2(float f, uint32_t& hi, uint32_t& lo) {
    float h = tf32r(f);
    hi = fbits(h);
    lo = fbits(tf32r(f - h));
}

// ---------------------------------------------------------------------------
// Projection: X @ W + b -> scatter [B,H,N,DH] (full fp32 outputs).
// ---------------------------------------------------------------------------
__global__ void proj_kernel(const float* __restrict__ x,
                            const float* __restrict__ Wq, const float* __restrict__ bq,
                            const float* __restrict__ Wk, const float* __restrict__ bk,
                            const float* __restrict__ Wv, const float* __restrict__ bv)
{
    __shared__ float As[16][132];
    __shared__ float Bs[16][132];
    const int tid = threadIdx.x;
    const int tx = tid & 15, ty = tid >> 4;
    const int m0 = blockIdx.x * 128;
    const int n0 = blockIdx.y * 128;
    const int which = blockIdx.z;

    const float* W    = (which == 0) ? Wq : (which == 1) ? Wk : Wv;
    const float* bias = (which == 0) ? bq : (which == 1) ? bk : bv;
    float* outp       = (which == 0) ? g_q : (which == 1) ? g_k : g_v;

    ull acc[8][4] = {};

    for (int k0 = 0; k0 < DIM; k0 += 16) {
        #pragma unroll
        for (int r = 0; r < 2; r++) {
            int p = tid + r * 256;
            int m = p >> 2, kg = (p & 3) * 4;
            int gm = m0 + m;
            float4 v = make_float4(0.f, 0.f, 0.f, 0.f);
            if (gm < NROWS) v = *(const float4*)&x[(size_t)gm * DIM + k0 + kg];
            As[kg + 0][m] = v.x; As[kg + 1][m] = v.y;
            As[kg + 2][m] = v.z; As[kg + 3][m] = v.w;
        }
        #pragma unroll
        for (int r = 0; r < 2; r++) {
            int p = tid + r * 256;
            int kk = p >> 5, ng = (p & 31) * 4;
            float4 v = *(const float4*)&W[(size_t)(k0 + kk) * HD + n0 + ng];
            *(float4*)&Bs[kk][ng] = v;
        }
        __syncthreads();
        #pragma unroll
        for (int kk = 0; kk < 16; kk++) {
            float4 a0 = *(const float4*)&As[kk][ty * 4];
            float4 a1 = *(const float4*)&As[kk][64 + ty * 4];
            ull aa[8];
            aa[0] = dup2(a0.x); aa[1] = dup2(a0.y); aa[2] = dup2(a0.z); aa[3] = dup2(a0.w);
            aa[4] = dup2(a1.x); aa[5] = dup2(a1.y); aa[6] = dup2(a1.z); aa[7] = dup2(a1.w);
            ull bb[4];
            bb[0] = *(const ull*)&Bs[kk][tx * 4];
            bb[1] = *(const ull*)&Bs[kk][tx * 4 + 2];
            bb[2] = *(const ull*)&Bs[kk][64 + tx * 4];
            bb[3] = *(const ull*)&Bs[kk][64 + tx * 4 + 2];
            #pragma unroll
            for (int i = 0; i < 8; i++)
                #pragma unroll
                for (int j = 0; j < 4; j++)
                    fma2(acc[i][j], aa[i], bb[j]);
        }
        __syncthreads();
    }

    #pragma unroll
    for (int i = 0; i < 8; i++) {
        int gm = m0 + ((i < 4) ? (ty * 4 + i) : (64 + ty * 4 + i - 4));
        if (gm >= NROWS) continue;
        int b = gm / NTOK, n = gm % NTOK;
        #pragma unroll
        for (int j = 0; j < 4; j++) {
            int c = (j < 2) ? (tx * 4 + j * 2) : (64 + tx * 4 + (j - 2) * 2);
            float2 v2 = unpack2(acc[i][j]);
            #pragma unroll
            for (int e = 0; e < 2; e++) {
                int gc = n0 + c + e;
                float v = ((e == 0) ? v2.x : v2.y) + bias[gc];
                if (which == 2) v = fmaxf(v, 0.f);
                int h = gc >> 6, d = gc & 63;
                outp[((size_t)((b * NH + h) * NTOK) + n) * DH + d] = v;
            }
        }
    }
}

// ---------------------------------------------------------------------------
// Scores via 3xTF32 mma.sync: per (bh, 128x128 tile): S = Q K^T * 0.125 + mask.
// Mask evaluated PER ELEMENT (frame boundaries are odd-aligned: JOINTS=25).
// ---------------------------------------------------------------------------
__global__ void __launch_bounds__(256) scores_mma(float* __restrict__ attn)
{
    extern __shared__ float sm[];
    float* Qs = sm;               // [128][68]
    float* Ks = sm + 128 * 68;    // [128][68]
    const int tid = threadIdx.x;
    const int m0 = blockIdx.x * 128, n0 = blockIdx.y * 128, bh = blockIdx.z;
    const float* Q = g_q + (size_t)bh * NTOK * DH;
    const float* K = g_k + (size_t)bh * NTOK * DH;
    const uint32_t qs_u = smem_u32(Qs), ks_u = smem_u32(Ks);

    #pragma unroll
    for (int r = 0; r < 8; r++) {
        int p = tid + r * 256;
        int row = p >> 4, ch = p & 15;
        int gq = m0 + row, gk = n0 + row;
        const float* sq = (gq < NTOK) ? &Q[(size_t)gq * DH + ch * 4] : Q;
        const float* sk = (gk < NTOK) ? &K[(size_t)gk * DH + ch * 4] : K;
        cpa16(qs_u + (row * 68 + ch * 4) * 4, sq, (gq < NTOK) ? 16 : 0);
        cpa16(ks_u + (row * 68 + ch * 4) * 4, sk, (gk < NTOK) ? 16 : 0);
    }
    cpa_commit();
    cpa_wait0();
    __syncthreads();

    const int w = tid >> 5, lane = tid & 31;
    const int wm = w & 3, wn = w >> 2;
    const int g = lane >> 2, tg = lane & 3;

    float acc[2][8][4] = {};
    #pragma unroll
    for (int ks = 0; ks < 8; ks++) {
        const int k = ks * 8;
        uint32_t ah[2][4], al[2][4];
        #pragma unroll
        for (int mt = 0; mt < 2; mt++) {
            const float* base = Qs + (wm * 32 + mt * 16 + g) * 68 + k + tg;
            split2(base[0],          ah[mt][0], al[mt][0]);
            split2(base[8 * 68],     ah[mt][1], al[mt][1]);
            split2(base[4],          ah[mt][2], al[mt][2]);
            split2(base[8 * 68 + 4], ah[mt][3], al[mt][3]);
        }
        #pragma unroll
        for (int nt = 0; nt < 8; nt++) {
            const float* base = Ks + (wn * 64 + nt * 8 + g) * 68 + k + tg;
            uint32_t bh_[2], bl_[2];
            split2(base[0], bh_[0], bl_[0]);
            split2(base[4], bh_[1], bl_[1]);
            #pragma unroll
            for (int mt = 0; mt < 2; mt++) {
                mma8(acc[mt][nt], ah[mt], bh_);
                mma8(acc[mt][nt], ah[mt], bl_);
                mma8(acc[mt][nt], al[mt], bh_);
            }
        }
    }

    float* Abh = attn + (size_t)bh * NTOK * NTOK;
    #pragma unroll
    for (int mt = 0; mt < 2; mt++) {
        #pragma unroll
        for (int i = 0; i < 2; i++) {
            int qn = m0 + wm * 32 + mt * 16 + g + i * 8;
            if (qn >= NTOK) continue;
            int qf = qn / JOINTS;
            float* rowp = Abh + (size_t)qn * NTOK;
            #pragma unroll
            for (int nt = 0; nt < 8; nt++) {
                int kn = n0 + wn * 64 + nt * 8 + tg * 2;
                if (kn >= NTOK) continue;    // pairs never straddle 3000
                float2 v;
                v.x = acc[mt][nt][i * 2 + 0] * 0.125f;
                v.y = acc[mt][nt][i * 2 + 1] * 0.125f;
                // per-element frame test (boundary can split a pair!)
                if ((kn       / JOINTS) == qf && kn     != qn) v.x = NEGV;
                if (((kn + 1) / JOINTS) == qf && kn + 1 != qn) v.y = NEGV;
                *(float2*)(rowp + kn) = v;
            }
        }
    }
}

// ---------------------------------------------------------------------------
// Row softmax in place.
// ---------------------------------------------------------------------------
__global__ void softmax_kernel(float* __restrict__ attn)
{
    const size_t row = blockIdx.x;
    float* p = attn + row * (size_t)NTOK;
    const int t = threadIdx.x;
    const int lane = t & 31, warp = t >> 5;
    __shared__ float red[4];

    float vals[24];
    float mx = NEGV;
    #pragma unroll
    for (int i = 0; i < 24; i++) {
        int idx = t + i * 128;
        float v = (idx < NTOK) ? p[idx] : NEGV;
        vals[i] = v;
        mx = fmaxf(mx, v);
    }
    #pragma unroll
    for (int o = 16; o; o >>= 1) mx = fmaxf(mx, __shfl_xor_sync(0xffffffffu, mx, o));
    if (lane == 0) red[warp] = mx;
    __syncthreads();
    mx = fmaxf(fmaxf(red[0], red[1]), fmaxf(red[2], red[3]));
    __syncthreads();

    float s = 0.f;
    #pragma unroll
    for (int i = 0; i < 24; i++) {
        float e = expf(vals[i] - mx);
        vals[i] = e;
        s += e;
    }
    #pragma unroll
    for (int o = 16; o; o >>= 1) s += __shfl_xor_sync(0xffffffffu, s, o);
    if (lane == 0) red[warp] = s;
    __syncthreads();
    s = red[0] + red[1] + red[2] + red[3];
    float inv = 1.f / s;

    #pragma unroll
    for (int i = 0; i < 24; i++) {
        int idx = t + i * 128;
        if (idx < NTOK) p[idx] = vals[i] * inv;
    }
}

// ---------------------------------------------------------------------------
// O = P @ V via 3xTF32 mma.sync. K=3000 streamed in 94 chunks of 32,
// cp.async double-buffered.
// ---------------------------------------------------------------------------
__global__ void __launch_bounds__(256) pv_mma(const float* __restrict__ attn,
                                              float* __restrict__ out)
{
    extern __shared__ float sm[];
    float* Ps = sm;                 // [2][128][36]
    float* Vs = sm + 2 * 128 * 36;  // [2][32][72]
    const int tid = threadIdx.x;
    const int m0 = blockIdx.x * 128, bh = blockIdx.z;
    const float* P = attn + (size_t)bh * NTOK * NTOK;
    const float* V = g_v + (size_t)bh * NTOK * DH;
    const uint32_t ps_u = smem_u32(Ps), vs_u = smem_u32(Vs);

    const int NCHUNK = (NTOK + 31) / 32;  // 94

    auto load_chunk = [&](int c) {
        const int k0 = c * 32;
        const int buf = c & 1;
        const uint32_t pd = ps_u + buf * 128 * 36 * 4;
        const uint32_t vd = vs_u + buf * 32 * 72 * 4;
        #pragma unroll
        for (int r = 0; r < 4; r++) {
            int p = tid + r * 256;
            int row = p >> 3, ch = p & 7;
            int gm = m0 + row, k = k0 + ch * 4;
            int bytes = 0;
            const float* src = P;
            if (gm < NTOK && k < NTOK) {
                int rem = (NTOK - k) * 4;
                bytes = rem >= 16 ? 16 : rem;
                src = &P[(size_t)gm * NTOK + k];
            }
            cpa16(pd + (row * 36 + ch * 4) * 4, src, bytes);
        }
        #pragma unroll
        for (int r = 0; r < 2; r++) {
            int p = tid + r * 256;
            int row = p >> 4, ch = p & 15;
            int tok = k0 + row;
            const float* src = (tok < NTOK) ? &V[(size_t)tok * DH + ch * 4] : V;
            cpa16(vd + (row * 72 + ch * 4) * 4, src, (tok < NTOK) ? 16 : 0);
        }
        cpa_commit();
    };

    load_chunk(0);

    const int w = tid >> 5, lane = tid & 31;
    const int wm = w & 3, wn = w >> 2;
    const int g = lane >> 2, tg = lane & 3;

    float acc[2][4][4] = {};

    for (int c = 0; c < NCHUNK; c++) {
        if (c + 1 < NCHUNK) { load_chunk(c + 1); cpa_wait1(); }
        else                { cpa_wait0(); }
        __syncthreads();

        const int buf = c & 1;
        const float* pb = Ps + buf * 128 * 36;
        const float* vb = Vs + buf * 32 * 72;

        #pragma unroll
        for (int ks = 0; ks < 4; ks++) {
            const int k = ks * 8;
            uint32_t ah[2][4], al[2][4];
            #pragma unroll
            for (int mt = 0; mt < 2; mt++) {
                const float* base = pb + (wm * 32 + mt * 16 + g) * 36 + k + tg;
                split2(base[0],          ah[mt][0], al[mt][0]);
                split2(base[8 * 36],     ah[mt][1], al[mt][1]);
                split2(base[4],          ah[mt][2], al[mt][2]);
                split2(base[8 * 36 + 4], ah[mt][3], al[mt][3]);
            }
            #pragma unroll
            for (int nt = 0; nt < 4; nt++) {
                const float* base = vb + (k + tg) * 72 + wn * 32 + nt * 8 + g;
                uint32_t bh_[2], bl_[2];
                split2(base[0],      bh_[0], bl_[0]);
                split2(base[4 * 72], bh_[1], bl_[1]);
                #pragma unroll
                for (int mt = 0; mt < 2; mt++) {
                    mma8(acc[mt][nt], ah[mt], bh_);
                    mma8(acc[mt][nt], ah[mt], bl_);
                    mma8(acc[mt][nt], al[mt], bh_);
                }
            }
        }
        __syncthreads();
    }

    const int bb = bh / NH, h = bh % NH;
    #pragma unroll
    for (int mt = 0; mt < 2; mt++) {
        #pragma unroll
        for (int i = 0; i < 2; i++) {
            int gm = m0 + wm * 32 + mt * 16 + g + i * 8;
            if (gm >= NTOK) continue;
            float* rowp = &out[((size_t)(bb * NTOK + gm)) * HD + h * DH];
            #pragma unroll
            for (int nt = 0; nt < 4; nt++) {
                int col = wn * 32 + nt * 8 + tg * 2;
                float2 v;
                v.x = acc[mt][nt][i * 2 + 0];
                v.y = acc[mt][nt][i * 2 + 1];
                *(float2*)(rowp + col) = v;
            }
        }
    }
}

// ---------------------------------------------------------------------------
extern "C" void kernel_launch(void* const* d_in, const int* in_sizes, int n_in,
                              void* d_out, int out_size)
{
    const float* x  = (const float*)d_in[0];
    const float* Wq = (const float*)d_in[1];
    const float* bq = (const float*)d_in[2];
    const float* Wk = (const float*)d_in[3];
    const float* bk = (const float*)d_in[4];
    const float* Wv = (const float*)d_in[5];
    const float* bv = (const float*)d_in[6];

    float* out  = (float*)d_out;
    float* attn = out + (size_t)BATCH * NTOK * HD;

    const int SMEM_SC = 2 * 128 * 68 * 4;                  // 69632
    const int SMEM_PV = (2 * 128 * 36 + 2 * 32 * 72) * 4;  // 55296
    cudaFuncSetAttribute(scores_mma, cudaFuncAttributeMaxDynamicSharedMemorySize, SMEM_SC);
    cudaFuncSetAttribute(pv_mma,     cudaFuncAttributeMaxDynamicSharedMemorySize, SMEM_PV);

    dim3 gproj((NROWS + 127) / 128, HD / 128, 3);
    proj_kernel<<<gproj, 256>>>(x, Wq, bq, Wk, bk, Wv, bv);

    dim3 gsc((NTOK + 127) / 128, (NTOK + 127) / 128, BATCH * NH);  // 24 x 24 x 32
    scores_mma<<<gsc, 256, SMEM_SC>>>(attn);

    softmax_kernel<<<BATCH * NH * NTOK, 128>>>(attn);

    dim3 go((NTOK + 127) / 128, 1, BATCH * NH);                    // 24 x 1 x 32
    pv_mma<<<go, 256, SMEM_PV>>>(attn, out);
}

// round 14
// speedup vs baseline: 2.3748x; 1.1854x over previous
#include <cuda_runtime.h>
#include <cstdint>
#include <math.h>

#define BATCH 4
#define JOINTS 25
#define NTOK 3000
#define DIM 512
#define NH 8
#define DH 64
#define HD 512
#define NROWS (BATCH*NTOK)
#define NEGV (-9e15f)

typedef unsigned long long ull;

// scratch: q,k,v in [B,H,N,DH] layout (full fp32)
__device__ float g_q[BATCH*NH*NTOK*DH];
__device__ float g_k[BATCH*NH*NTOK*DH];
__device__ float g_v[BATCH*NH*NTOK*DH];

// ---------------- f32x2 helpers (proj kernel) ------------------------------
__device__ __forceinline__ ull dup2(float x) {
    ull r; asm("mov.b64 %0, {%1, %1};" : "=l"(r) : "f"(x)); return r;
}
__device__ __forceinline__ void fma2(ull& d, ull a, ull b) {
    asm("fma.rn.f32x2 %0, %1, %2, %0;" : "+l"(d) : "l"(a), "l"(b));
}
__device__ __forceinline__ float2 unpack2(ull v) {
    float2 f; asm("mov.b64 {%0, %1}, %2;" : "=f"(f.x), "=f"(f.y) : "l"(v)); return f;
}
__device__ __forceinline__ float tf32r(float x) {
    float r; asm("cvt.rna.tf32.f32 %0, %1;" : "=f"(r) : "f"(x)); return r;
}

// ---------------- cp.async + mma.sync helpers ------------------------------
__device__ __forceinline__ uint32_t smem_u32(const void* p) {
    uint32_t a;
    asm("{ .reg .u64 t; cvta.to.shared.u64 t, %1; cvt.u32.u64 %0, t; }" : "=r"(a) : "l"(p));
    return a;
}
__device__ __forceinline__ void cpa16(uint32_t dst, const void* src, int bytes) {
    asm volatile("cp.async.ca.shared.global [%0], [%1], 16, %2;"
                 :: "r"(dst), "l"(src), "r"(bytes) : "memory");
}
__device__ __forceinline__ void cpa_commit() {
    asm volatile("cp.async.commit_group;" ::: "memory");
}
__device__ __forceinline__ void cpa_wait0() {
    asm volatile("cp.async.wait_group 0;" ::: "memory");
}
__device__ __forceinline__ void cpa_wait1() {
    asm volatile("cp.async.wait_group 1;" ::: "memory");
}
// D += A(16x8) * B(8x8), tf32 inputs, f32 accum
__device__ __forceinline__ void mma8(float* c, const uint32_t* a, const uint32_t* b) {
    asm volatile(
        "mma.sync.aligned.m16n8k8.row.col.f32.tf32.tf32.f32 "
        "{%0,%1,%2,%3}, {%4,%5,%6,%7}, {%8,%9}, {%0,%1,%2,%3};"
        : "+f"(c[0]), "+f"(c[1]), "+f"(c[2]), "+f"(c[3])
        : "r"(a[0]), "r"(a[1]), "r"(a[2]), "r"(a[3]), "r"(b[0]), "r"(b[1]));
}
__device__ __forceinline__ uint32_t fbits(float x) {
    uint32_t u; asm("mov.b32 %0, %1;" : "=r"(u) : "f"(x)); return u;
}
// split fp32 into tf32 hi + tf32 lo (3xTF32 decomposition)
__device__ __forceinline__ void split2(float f, uint32_t& hi, uint32_t& lo) {
    float h = tf32r(f);
    hi = fbits(h);
    lo = fbits(tf32r(f - h));
}
// single tf32 truncation for fragment load
__device__ __forceinline__ uint32_t t1(float f) { return fbits(tf32r(f)); }

// ---------------------------------------------------------------------------
// Projection: X @ W + b -> scatter [B,H,N,DH] (full fp32 outputs).
// ---------------------------------------------------------------------------
__global__ void proj_kernel(const float* __restrict__ x,
                            const float* __restrict__ Wq, const float* __restrict__ bq,
                            const float* __restrict__ Wk, const float* __restrict__ bk,
                            const float* __restrict__ Wv, const float* __restrict__ bv)
{
    __shared__ float As[16][132];
    __shared__ float Bs[16][132];
    const int tid = threadIdx.x;
    const int tx = tid & 15, ty = tid >> 4;
    const int m0 = blockIdx.x * 128;
    const int n0 = blockIdx.y * 128;
    const int which = blockIdx.z;

    const float* W    = (which == 0) ? Wq : (which == 1) ? Wk : Wv;
    const float* bias = (which == 0) ? bq : (which == 1) ? bk : bv;
    float* outp       = (which == 0) ? g_q : (which == 1) ? g_k : g_v;

    ull acc[8][4] = {};

    for (int k0 = 0; k0 < DIM; k0 += 16) {
        #pragma unroll
        for (int r = 0; r < 2; r++) {
            int p = tid + r * 256;
            int m = p >> 2, kg = (p & 3) * 4;
            int gm = m0 + m;
            float4 v = make_float4(0.f, 0.f, 0.f, 0.f);
            if (gm < NROWS) v = *(const float4*)&x[(size_t)gm * DIM + k0 + kg];
            As[kg + 0][m] = v.x; As[kg + 1][m] = v.y;
            As[kg + 2][m] = v.z; As[kg + 3][m] = v.w;
        }
        #pragma unroll
        for (int r = 0; r < 2; r++) {
            int p = tid + r * 256;
            int kk = p >> 5, ng = (p & 31) * 4;
            float4 v = *(const float4*)&W[(size_t)(k0 + kk) * HD + n0 + ng];
            *(float4*)&Bs[kk][ng] = v;
        }
        __syncthreads();
        #pragma unroll
        for (int kk = 0; kk < 16; kk++) {
            float4 a0 = *(const float4*)&As[kk][ty * 4];
            float4 a1 = *(const float4*)&As[kk][64 + ty * 4];
            ull aa[8];
            aa[0] = dup2(a0.x); aa[1] = dup2(a0.y); aa[2] = dup2(a0.z); aa[3] = dup2(a0.w);
            aa[4] = dup2(a1.x); aa[5] = dup2(a1.y); aa[6] = dup2(a1.z); aa[7] = dup2(a1.w);
            ull bb[4];
            bb[0] = *(const ull*)&Bs[kk][tx * 4];
            bb[1] = *(const ull*)&Bs[kk][tx * 4 + 2];
            bb[2] = *(const ull*)&Bs[kk][64 + tx * 4];
            bb[3] = *(const ull*)&Bs[kk][64 + tx * 4 + 2];
            #pragma unroll
            for (int i = 0; i < 8; i++)
                #pragma unroll
                for (int j = 0; j < 4; j++)
                    fma2(acc[i][j], aa[i], bb[j]);
        }
        __syncthreads();
    }

    #pragma unroll
    for (int i = 0; i < 8; i++) {
        int gm = m0 + ((i < 4) ? (ty * 4 + i) : (64 + ty * 4 + i - 4));
        if (gm >= NROWS) continue;
        int b = gm / NTOK, n = gm % NTOK;
        #pragma unroll
        for (int j = 0; j < 4; j++) {
            int c = (j < 2) ? (tx * 4 + j * 2) : (64 + tx * 4 + (j - 2) * 2);
            float2 v2 = unpack2(acc[i][j]);
            #pragma unroll
            for (int e = 0; e < 2; e++) {
                int gc = n0 + c + e;
                float v = ((e == 0) ? v2.x : v2.y) + bias[gc];
                if (which == 2) v = fmaxf(v, 0.f);
                int h = gc >> 6, d = gc & 63;
                outp[((size_t)((b * NH + h) * NTOK) + n) * DH + d] = v;
            }
        }
    }
}

// ---------------------------------------------------------------------------
// Scores via 3xTF32 mma.sync: per (bh, 128x128 tile): S = Q K^T * 0.125 + mask.
// Mask evaluated PER ELEMENT (frame boundaries are odd-aligned: JOINTS=25).
// ---------------------------------------------------------------------------
__global__ void __launch_bounds__(256) scores_mma(float* __restrict__ attn)
{
    extern __shared__ float sm[];
    float* Qs = sm;               // [128][68]
    float* Ks = sm + 128 * 68;    // [128][68]
    const int tid = threadIdx.x;
    const int m0 = blockIdx.x * 128, n0 = blockIdx.y * 128, bh = blockIdx.z;
    const float* Q = g_q + (size_t)bh * NTOK * DH;
    const float* K = g_k + (size_t)bh * NTOK * DH;
    const uint32_t qs_u = smem_u32(Qs), ks_u = smem_u32(Ks);

    #pragma unroll
    for (int r = 0; r < 8; r++) {
        int p = tid + r * 256;
        int row = p >> 4, ch = p & 15;
        int gq = m0 + row, gk = n0 + row;
        const float* sq = (gq < NTOK) ? &Q[(size_t)gq * DH + ch * 4] : Q;
        const float* sk = (gk < NTOK) ? &K[(size_t)gk * DH + ch * 4] : K;
        cpa16(qs_u + (row * 68 + ch * 4) * 4, sq, (gq < NTOK) ? 16 : 0);
        cpa16(ks_u + (row * 68 + ch * 4) * 4, sk, (gk < NTOK) ? 16 : 0);
    }
    cpa_commit();
    cpa_wait0();
    __syncthreads();

    const int w = tid >> 5, lane = tid & 31;
    const int wm = w & 3, wn = w >> 2;
    const int g = lane >> 2, tg = lane & 3;

    float acc[2][8][4] = {};
    #pragma unroll
    for (int ks = 0; ks < 8; ks++) {
        const int k = ks * 8;
        uint32_t ah[2][4], al[2][4];
        #pragma unroll
        for (int mt = 0; mt < 2; mt++) {
            const float* base = Qs + (wm * 32 + mt * 16 + g) * 68 + k + tg;
            split2(base[0],          ah[mt][0], al[mt][0]);
            split2(base[8 * 68],     ah[mt][1], al[mt][1]);
            split2(base[4],          ah[mt][2], al[mt][2]);
            split2(base[8 * 68 + 4], ah[mt][3], al[mt][3]);
        }
        #pragma unroll
        for (int nt = 0; nt < 8; nt++) {
            const float* base = Ks + (wn * 64 + nt * 8 + g) * 68 + k + tg;
            uint32_t bh_[2], bl_[2];
            split2(base[0], bh_[0], bl_[0]);
            split2(base[4], bh_[1], bl_[1]);
            #pragma unroll
            for (int mt = 0; mt < 2; mt++) {
                mma8(acc[mt][nt], ah[mt], bh_);
                mma8(acc[mt][nt], ah[mt], bl_);
                mma8(acc[mt][nt], al[mt], bh_);
            }
        }
    }

    float* Abh = attn + (size_t)bh * NTOK * NTOK;
    #pragma unroll
    for (int mt = 0; mt < 2; mt++) {
        #pragma unroll
        for (int i = 0; i < 2; i++) {
            int qn = m0 + wm * 32 + mt * 16 + g + i * 8;
            if (qn >= NTOK) continue;
            int qf = qn / JOINTS;
            float* rowp = Abh + (size_t)qn * NTOK;
            #pragma unroll
            for (int nt = 0; nt < 8; nt++) {
                int kn = n0 + wn * 64 + nt * 8 + tg * 2;
                if (kn >= NTOK) continue;    // pairs never straddle 3000
                float2 v;
                v.x = acc[mt][nt][i * 2 + 0] * 0.125f;
                v.y = acc[mt][nt][i * 2 + 1] * 0.125f;
                // per-element frame test (boundary can split a pair!)
                if ((kn       / JOINTS) == qf && kn     != qn) v.x = NEGV;
                if (((kn + 1) / JOINTS) == qf && kn + 1 != qn) v.y = NEGV;
                *(float2*)(rowp + kn) = v;
            }
        }
    }
}

// ---------------------------------------------------------------------------
// Row softmax in place: 256 threads, 12 values/thread, __expf.
// ---------------------------------------------------------------------------
__global__ void __launch_bounds__(256) softmax_kernel(float* __restrict__ attn)
{
    const size_t row = blockIdx.x;
    float* p = attn + row * (size_t)NTOK;
    const int t = threadIdx.x;
    const int lane = t & 31, warp = t >> 5;
    __shared__ float red[8];

    float vals[12];
    float mx = NEGV;
    #pragma unroll
    for (int i = 0; i < 12; i++) {
        int idx = t + i * 256;
        float v = (idx < NTOK) ? p[idx] : NEGV;
        vals[i] = v;
        mx = fmaxf(mx, v);
    }
    #pragma unroll
    for (int o = 16; o; o >>= 1) mx = fmaxf(mx, __shfl_xor_sync(0xffffffffu, mx, o));
    if (lane == 0) red[warp] = mx;
    __syncthreads();
    mx = fmaxf(fmaxf(fmaxf(red[0], red[1]), fmaxf(red[2], red[3])),
               fmaxf(fmaxf(red[4], red[5]), fmaxf(red[6], red[7])));
    __syncthreads();

    float s = 0.f;
    #pragma unroll
    for (int i = 0; i < 12; i++) {
        float e = __expf(vals[i] - mx);   // masked (-9e15) -> exactly 0
        vals[i] = e;
        s += e;
    }
    #pragma unroll
    for (int o = 16; o; o >>= 1) s += __shfl_xor_sync(0xffffffffu, s, o);
    if (lane == 0) red[warp] = s;
    __syncthreads();
    s = (red[0] + red[1]) + (red[2] + red[3]) + (red[4] + red[5]) + (red[6] + red[7]);
    float inv = 1.f / s;

    #pragma unroll
    for (int i = 0; i < 12; i++) {
        int idx = t + i * 256;
        if (idx < NTOK) p[idx] = vals[i] * inv;
    }
}

// ---------------------------------------------------------------------------
// O = P @ V via SINGLE-PASS tf32 mma.sync (P >= 0 and V >= 0 after ReLU:
// truncation errors enter as a weighted average and cancel to ~1e-5).
// K=3000 streamed in 94 chunks of 32, cp.async double-buffered.
// ---------------------------------------------------------------------------
__global__ void __launch_bounds__(256) pv_mma(const float* __restrict__ attn,
                                              float* __restrict__ out)
{
    extern __shared__ float sm[];
    float* Ps = sm;                 // [2][128][36]
    float* Vs = sm + 2 * 128 * 36;  // [2][32][72]
    const int tid = threadIdx.x;
    const int m0 = blockIdx.x * 128, bh = blockIdx.z;
    const float* P = attn + (size_t)bh * NTOK * NTOK;
    const float* V = g_v + (size_t)bh * NTOK * DH;
    const uint32_t ps_u = smem_u32(Ps), vs_u = smem_u32(Vs);

    const int NCHUNK = (NTOK + 31) / 32;  // 94

    auto load_chunk = [&](int c) {
        const int k0 = c * 32;
        const int buf = c & 1;
        const uint32_t pd = ps_u + buf * 128 * 36 * 4;
        const uint32_t vd = vs_u + buf * 32 * 72 * 4;
        #pragma unroll
        for (int r = 0; r < 4; r++) {
            int p = tid + r * 256;
            int row = p >> 3, ch = p & 7;
            int gm = m0 + row, k = k0 + ch * 4;
            int bytes = 0;
            const float* src = P;
            if (gm < NTOK && k < NTOK) {
                int rem = (NTOK - k) * 4;
                bytes = rem >= 16 ? 16 : rem;
                src = &P[(size_t)gm * NTOK + k];
            }
            cpa16(pd + (row * 36 + ch * 4) * 4, src, bytes);
        }
        #pragma unroll
        for (int r = 0; r < 2; r++) {
            int p = tid + r * 256;
            int row = p >> 4, ch = p & 15;
            int tok = k0 + row;
            const float* src = (tok < NTOK) ? &V[(size_t)tok * DH + ch * 4] : V;
            cpa16(vd + (row * 72 + ch * 4) * 4, src, (tok < NTOK) ? 16 : 0);
        }
        cpa_commit();
    };

    load_chunk(0);

    const int w = tid >> 5, lane = tid & 31;
    const int wm = w & 3, wn = w >> 2;
    const int g = lane >> 2, tg = lane & 3;

    float acc[2][4][4] = {};

    for (int c = 0; c < NCHUNK; c++) {
        if (c + 1 < NCHUNK) { load_chunk(c + 1); cpa_wait1(); }
        else                { cpa_wait0(); }
        __syncthreads();

        const int buf = c & 1;
        const float* pb = Ps + buf * 128 * 36;
        const float* vb = Vs + buf * 32 * 72;

        #pragma unroll
        for (int ks = 0; ks < 4; ks++) {
            const int k = ks * 8;
            uint32_t a[2][4];
            #pragma unroll
            for (int mt = 0; mt < 2; mt++) {
                const float* base = pb + (wm * 32 + mt * 16 + g) * 36 + k + tg;
                a[mt][0] = t1(base[0]);
                a[mt][1] = t1(base[8 * 36]);
                a[mt][2] = t1(base[4]);
                a[mt][3] = t1(base[8 * 36 + 4]);
            }
            #pragma unroll
            for (int nt = 0; nt < 4; nt++) {
                const float* base = vb + (k + tg) * 72 + wn * 32 + nt * 8 + g;
                uint32_t b[2];
                b[0] = t1(base[0]);
                b[1] = t1(base[4 * 72]);
                #pragma unroll
                for (int mt = 0; mt < 2; mt++)
                    mma8(acc[mt][nt], a[mt], b);
            }
        }
        __syncthreads();
    }

    const int bb = bh / NH, h = bh % NH;
    #pragma unroll
    for (int mt = 0; mt < 2; mt++) {
        #pragma unroll
        for (int i = 0; i < 2; i++) {
            int gm = m0 + wm * 32 + mt * 16 + g + i * 8;
            if (gm >= NTOK) continue;
            float* rowp = &out[((size_t)(bb * NTOK + gm)) * HD + h * DH];
            #pragma unroll
            for (int nt = 0; nt < 4; nt++) {
                int col = wn * 32 + nt * 8 + tg * 2;
                float2 v;
                v.x = acc[mt][nt][i * 2 + 0];
                v.y = acc[mt][nt][i * 2 + 1];
                *(float2*)(rowp + col) = v;
            }
        }
    }
}

// ---------------------------------------------------------------------------
extern "C" void kernel_launch(void* const* d_in, const int* in_sizes, int n_in,
                              void* d_out, int out_size)
{
    const float* x  = (const float*)d_in[0];
    const float* Wq = (const float*)d_in[1];
    const float* bq = (const float*)d_in[2];
    const float* Wk = (const float*)d_in[3];
    const float* bk = (const float*)d_in[4];
    const float* Wv = (const float*)d_in[5];
    const float* bv = (const float*)d_in[6];

    float* out  = (float*)d_out;
    float* attn = out + (size_t)BATCH * NTOK * HD;

    const int SMEM_SC = 2 * 128 * 68 * 4;                  // 69632
    const int SMEM_PV = (2 * 128 * 36 + 2 * 32 * 72) * 4;  // 55296
    cudaFuncSetAttribute(scores_mma, cudaFuncAttributeMaxDynamicSharedMemorySize, SMEM_SC);
    cudaFuncSetAttribute(pv_mma,     cudaFuncAttributeMaxDynamicSharedMemorySize, SMEM_PV);

    dim3 gproj((NROWS + 127) / 128, HD / 128, 3);
    proj_kernel<<<gproj, 256>>>(x, Wq, bq, Wk, bk, Wv, bv);

    dim3 gsc((NTOK + 127) / 128, (NTOK + 127) / 128, BATCH * NH);  // 24 x 24 x 32
    scores_mma<<<gsc, 256, SMEM_SC>>>(attn);

    softmax_kernel<<<BATCH * NH * NTOK, 256>>>(attn);

    dim3 go((NTOK + 127) / 128, 1, BATCH * NH);                    // 24 x 1 x 32
    pv_mma<<<go, 256, SMEM_PV>>>(attn, out);
}